// round 1
// baseline (speedup 1.0000x reference)
#include <cuda_runtime.h>
#include <cuda_bf16.h>
#include <math.h>

namespace {

constexpr int F = 3, B = 64, C = 16, D = 512;
constexpr int CD = C * D;                 // 8192
constexpr float EPSF = 1e-8f;
constexpr float NEGINF = -1e30f;
constexpr float INV_T = 10.0f;            // 1 / 0.1

// Scratch (device globals: no allocation allowed in kernel_launch)
__device__ __align__(16) __nv_bfloat16 g_bi[F * B * CD];   // bf16 copy of fmaps_i
__device__ __align__(16) __nv_bfloat16 g_bj[F * B * CD];   // bf16 copy of fmaps_j
__device__ float g_rni[F * B * C];        // per-channel ||.||^2 of fmaps_i (fp32)
__device__ float g_rnj[F * B * C];        // per-channel ||.||^2 of fmaps_j (fp32)
__device__ float g_an[F * B];             // anchor norms (fp32)
__device__ float g_pos[F * B];            // pos_sim / T
__device__ float g_sim[2 * F * B * B];    // [type][f][i][j] similarity logits

__device__ __forceinline__ float warpsum(float v) {
#pragma unroll
    for (int o = 16; o; o >>= 1) v += __shfl_down_sync(0xffffffffu, v, o);
    return v;
}

__device__ __forceinline__ float dot2(unsigned a, unsigned b) {
    __nv_bfloat162 ba = *reinterpret_cast<__nv_bfloat162*>(&a);
    __nv_bfloat162 bb = *reinterpret_cast<__nv_bfloat162*>(&b);
    float2 fa = __bfloat1622float2(ba);
    float2 fb = __bfloat1622float2(bb);
    return fmaf(fa.x, fb.x, fa.y * fb.y);
}

__device__ __forceinline__ float dot8(uint4 a, uint4 b) {
    return (dot2(a.x, b.x) + dot2(a.y, b.y)) + (dot2(a.z, b.z) + dot2(a.w, b.w));
}

// ---------------------------------------------------------------------------
// Kernel 1: fp32 -> bf16 conversion + per-channel squared norms (fp32)
// grid = 2*F*B*C blocks of 128 threads (one block per channel, both banks)
// ---------------------------------------------------------------------------
__global__ void k_convert(const float* __restrict__ fi, const float* __restrict__ fj) {
    int bid = blockIdx.x;
    int half = (bid >= F * B * C) ? 1 : 0;
    int ch = half ? (bid - F * B * C) : bid;
    const float4* src = reinterpret_cast<const float4*>((half ? fj : fi) + (size_t)ch * D);
    __nv_bfloat162* dst = reinterpret_cast<__nv_bfloat162*>((half ? g_bj : g_bi) + (size_t)ch * D);
    float* rn = half ? g_rnj : g_rni;

    int t = threadIdx.x;                           // 128 threads * 4 floats = 512
    float4 v = src[t];
    dst[2 * t]     = __floats2bfloat162_rn(v.x, v.y);
    dst[2 * t + 1] = __floats2bfloat162_rn(v.z, v.w);

    float ss = v.x * v.x + v.y * v.y + v.z * v.z + v.w * v.w;
    ss = warpsum(ss);
    __shared__ float s[4];
    if ((t & 31) == 0) s[t >> 5] = ss;
    __syncthreads();
    if (t == 0) rn[ch] = s[0] + s[1] + s[2] + s[3];
}

// ---------------------------------------------------------------------------
// Kernel 2: pos_sim (fp32, full precision) + anchor norms
// grid = F*B blocks of 256 threads
// ---------------------------------------------------------------------------
__global__ void k_pos(const float* __restrict__ fi, const float* __restrict__ fj) {
    int fb = blockIdx.x;
    const float4* a = reinterpret_cast<const float4*>(fi + (size_t)fb * CD);
    const float4* p = reinterpret_cast<const float4*>(fj + (size_t)fb * CD);
    float dot = 0.f, sa = 0.f, sb = 0.f;
    for (int k = threadIdx.x; k < CD / 4; k += 256) {
        float4 x = a[k], y = p[k];
        dot += x.x * y.x + x.y * y.y + x.z * y.z + x.w * y.w;
        sa  += x.x * x.x + x.y * x.y + x.z * x.z + x.w * x.w;
        sb  += y.x * y.x + y.y * y.y + y.z * y.z + y.w * y.w;
    }
    dot = warpsum(dot); sa = warpsum(sa); sb = warpsum(sb);
    __shared__ float sd[8], ssa[8], ssb[8];
    int w = threadIdx.x >> 5, l = threadIdx.x & 31;
    if (!l) { sd[w] = dot; ssa[w] = sa; ssb[w] = sb; }
    __syncthreads();
    if (threadIdx.x == 0) {
        float td = 0.f, ta = 0.f, tb = 0.f;
#pragma unroll
        for (int w2 = 0; w2 < 8; w2++) { td += sd[w2]; ta += ssa[w2]; tb += ssb[w2]; }
        float na = sqrtf(ta), nb = sqrtf(tb);
        g_an[fb]  = na;
        g_pos[fb] = td / (fmaxf(na, EPSF) * fmaxf(nb, EPSF)) * INV_T;
    }
}

// ---------------------------------------------------------------------------
// Kernel 3: gathered negative similarities (the hot kernel)
// grid = F*B*2*2 = 768 blocks of 128 threads (4 warps).
// block = (f, i, type, jhalf); each warp loops over 8 of the 32 j's.
// Anchor (16KB bf16) + indices + channel norms live in smem.
// ---------------------------------------------------------------------------
__global__ void __launch_bounds__(128) k_neg(const int* __restrict__ ids_raw,
                                             const int* __restrict__ idxj,
                                             const int* __restrict__ idxk) {
    int bid = blockIdx.x;
    int jhalf = bid & 1;
    int type  = (bid >> 1) & 1;
    int i = (bid >> 2) % B;
    int f = bid / (4 * B);

    const __nv_bfloat16* bank = type ? g_bi : g_bj;
    const float* rn = type ? g_rni : g_rnj;
    const int* idx = type ? idxk : idxj;
    float* out = g_sim + ((size_t)(type * F + f) * B + i) * B;

    __shared__ uint4 sA[CD / 8];        // anchor: 1024 * 16B = 16KB
    __shared__ int   sIdx[32 * C];      // 2KB
    __shared__ float sRn[32 * C];       // 2KB

    const uint4* aGlob = reinterpret_cast<const uint4*>(g_bi + (size_t)(f * B + i) * CD);
    for (int k = threadIdx.x; k < CD / 8; k += 128) sA[k] = aGlob[k];
    const int* idxBase = idx + ((size_t)(f * B + i) * B + jhalf * 32) * C;
    for (int k = threadIdx.x; k < 32 * C; k += 128) sIdx[k] = idxBase[k];
    const float* rnBase = rn + (size_t)(f * B + jhalf * 32) * C;
    for (int k = threadIdx.x; k < 32 * C; k += 128) sRn[k] = rnBase[k];
    __syncthreads();

    int warp = threadIdx.x >> 5, lane = threadIdx.x & 31;

    // partnet_ids may be int32 or int64 depending on jax x64 config.
    // int64 small values => high words (odd int32 slots) are zero.
    bool is64 = (ids_raw[1] == 0) && (ids_raw[3] == 0) && (ids_raw[5] == 0) && (ids_raw[7] == 0);
    const long long* ids64 = reinterpret_cast<const long long*>(ids_raw);
    long long myid = is64 ? ids64[i] : (long long)ids_raw[i];

    float na = fmaxf(g_an[f * B + i], EPSF);

    for (int jj = warp; jj < 32; jj += 4) {
        int j = jhalf * 32 + jj;
        long long jid = is64 ? ids64[j] : (long long)ids_raw[j];
        if (j == i || jid == myid) {
            if (!lane) out[j] = NEGINF;
            continue;
        }
        const uint4* gbase = reinterpret_cast<const uint4*>(bank + (size_t)(f * B + j) * CD);
        float acc = 0.f, nsq = 0.f;
#pragma unroll
        for (int c = 0; c < C; c++) {
            int cc = sIdx[jj * C + c];
            const uint4* gp = gbase + cc * (D / 8);    // 64 uint4 per channel
            uint4 v0 = gp[lane];
            uint4 v1 = gp[lane + 32];
            uint4 a0 = sA[c * 64 + lane];
            uint4 a1 = sA[c * 64 + lane + 32];
            acc += dot8(v0, a0) + dot8(v1, a1);
            if (!lane) nsq += sRn[jj * C + cc];
        }
        acc = warpsum(acc);
        if (!lane) {
            float nb = fmaxf(sqrtf(nsq), EPSF);
            out[j] = acc / (na * nb) * INV_T;
        }
    }
}

// ---------------------------------------------------------------------------
// Kernel 4: logsumexp over [pos, 2B negs] per (f,i), sum, scale. Single CTA.
// ---------------------------------------------------------------------------
__global__ void k_final(float* __restrict__ out) {
    int t = threadIdx.x;   // 256
    float loss = 0.f;
    if (t < F * B) {
        float p = g_pos[t];
        const float* sj = g_sim + (size_t)t * B;
        const float* sk = g_sim + (size_t)F * B * B + (size_t)t * B;
        float m = p;
        for (int j = 0; j < B; j++) { m = fmaxf(m, sj[j]); m = fmaxf(m, sk[j]); }
        float s = expf(p - m);
        for (int j = 0; j < B; j++) s += expf(sj[j] - m) + expf(sk[j] - m);
        loss = logf(s) + m - p;
    }
    loss = warpsum(loss);
    __shared__ float sm[8];
    if (!(t & 31)) sm[t >> 5] = loss;
    __syncthreads();
    if (t == 0) {
        float tot = 0.f;
#pragma unroll
        for (int w = 0; w < 8; w++) tot += sm[w];
        out[0] = tot * (1.0f / 128.0f);   // / (2 * BATCH_SIZE)
    }
}

}  // namespace

extern "C" void kernel_launch(void* const* d_in, const int* in_sizes, int n_in,
                              void* d_out, int out_size) {
    const float* fi   = (const float*)d_in[0];
    const float* fj   = (const float*)d_in[1];
    const int*   ids  = (const int*)d_in[2];   // int32 or int64; detected in-kernel
    const int*   idxj = (const int*)d_in[3];
    const int*   idxk = (const int*)d_in[4];
    float* out = (float*)d_out;

    k_convert<<<2 * F * B * C, 128>>>(fi, fj);
    k_pos<<<F * B, 256>>>(fi, fj);
    k_neg<<<F * B * 4, 128>>>(ids, idxj, idxk);
    k_final<<<1, 256>>>(out);
}

// round 5
// speedup vs baseline: 1.5761x; 1.5761x over previous
#include <cuda_runtime.h>
#include <cuda_bf16.h>
#include <cstdint>
#include <math.h>

namespace {

constexpr int F = 3, B = 64, C = 16, D = 512;
constexpr int CD = C * D;                 // 8192
constexpr int BC = B * C;                 // 1024 (Gram dimension)
constexpr float EPSF = 1e-8f;
constexpr float NEGINF = -1e30f;
constexpr float INV_T = 10.0f;            // 1 / 0.1

// ---- device scratch (no allocation allowed) ----
__device__ __align__(16) __nv_bfloat16 g_bi[F * B * CD];   // bf16 fmaps_i
__device__ __align__(16) __nv_bfloat16 g_bj[F * B * CD];   // bf16 fmaps_j
__device__ float g_rni[F * B * C];        // per-channel ||.||^2 fmaps_i
__device__ float g_rnj[F * B * C];        // per-channel ||.||^2 fmaps_j
__device__ float g_an[F * B];             // anchor norms
__device__ float g_pos[F * B];            // pos_sim / T
__device__ __align__(16) float g_gram[6 * BC * BC];  // [f*2+type][1024][1024]
__device__ float g_sim[2 * F * B * B];    // [type][f][i][j]
__device__ float g_loss[F * B];

__device__ __forceinline__ float warpsum(float v) {
#pragma unroll
    for (int o = 16; o; o >>= 1) v += __shfl_down_sync(0xffffffffu, v, o);
    return v;
}
__device__ __forceinline__ float warpmax(float v) {
#pragma unroll
    for (int o = 16; o; o >>= 1) v = fmaxf(v, __shfl_xor_sync(0xffffffffu, v, o));
    return v;
}

__device__ __forceinline__ uint32_t smem_u32(const void* p) {
    uint32_t a;
    asm("{ .reg .u64 t; cvta.to.shared.u64 t, %1; cvt.u32.u64 %0, t; }" : "=r"(a) : "l"(p));
    return a;
}
__device__ __forceinline__ void ldsm4(uint32_t* r, uint32_t addr) {
    asm volatile("ldmatrix.sync.aligned.m8n8.x4.shared.b16 {%0,%1,%2,%3}, [%4];"
        : "=r"(r[0]), "=r"(r[1]), "=r"(r[2]), "=r"(r[3]) : "r"(addr));
}
__device__ __forceinline__ void mma16816(float* c, const uint32_t* a,
                                         uint32_t b0, uint32_t b1) {
    asm volatile(
        "mma.sync.aligned.m16n8k16.row.col.f32.bf16.bf16.f32 "
        "{%0,%1,%2,%3}, {%4,%5,%6,%7}, {%8,%9}, {%0,%1,%2,%3};"
        : "+f"(c[0]), "+f"(c[1]), "+f"(c[2]), "+f"(c[3])
        : "r"(a[0]), "r"(a[1]), "r"(a[2]), "r"(a[3]), "r"(b0), "r"(b1));
}

// ---------------------------------------------------------------------------
// Kernel 1: fp32 -> bf16 + per-channel squared norms
// ---------------------------------------------------------------------------
__global__ void k_convert(const float* __restrict__ fi, const float* __restrict__ fj) {
    int bid = blockIdx.x;
    int half = (bid >= F * B * C) ? 1 : 0;
    int ch = half ? (bid - F * B * C) : bid;
    const float4* src = reinterpret_cast<const float4*>((half ? fj : fi) + (size_t)ch * D);
    __nv_bfloat162* dst = reinterpret_cast<__nv_bfloat162*>((half ? g_bj : g_bi) + (size_t)ch * D);
    float* rn = half ? g_rnj : g_rni;

    int t = threadIdx.x;                           // 128 threads * 4 floats = 512
    float4 v = src[t];
    dst[2 * t]     = __floats2bfloat162_rn(v.x, v.y);
    dst[2 * t + 1] = __floats2bfloat162_rn(v.z, v.w);

    float ss = v.x * v.x + v.y * v.y + v.z * v.z + v.w * v.w;
    ss = warpsum(ss);
    __shared__ float s[4];
    if ((t & 31) == 0) s[t >> 5] = ss;
    __syncthreads();
    if (t == 0) rn[ch] = s[0] + s[1] + s[2] + s[3];
}

// ---------------------------------------------------------------------------
// Kernel 2: pos_sim (full fp32) + anchor norms
// ---------------------------------------------------------------------------
__global__ void k_pos(const float* __restrict__ fi, const float* __restrict__ fj) {
    int fb = blockIdx.x;
    const float4* a = reinterpret_cast<const float4*>(fi + (size_t)fb * CD);
    const float4* p = reinterpret_cast<const float4*>(fj + (size_t)fb * CD);
    float dot = 0.f, sa = 0.f, sb = 0.f;
    for (int k = threadIdx.x; k < CD / 4; k += 256) {
        float4 x = a[k], y = p[k];
        dot += x.x * y.x + x.y * y.y + x.z * y.z + x.w * y.w;
        sa  += x.x * x.x + x.y * x.y + x.z * x.z + x.w * x.w;
        sb  += y.x * y.x + y.y * y.y + y.z * y.z + y.w * y.w;
    }
    dot = warpsum(dot); sa = warpsum(sa); sb = warpsum(sb);
    __shared__ float sd[8], ssa[8], ssb[8];
    int w = threadIdx.x >> 5, l = threadIdx.x & 31;
    if (!l) { sd[w] = dot; ssa[w] = sa; ssb[w] = sb; }
    __syncthreads();
    if (threadIdx.x == 0) {
        float td = 0.f, ta = 0.f, tb = 0.f;
#pragma unroll
        for (int w2 = 0; w2 < 8; w2++) { td += sd[w2]; ta += ssa[w2]; tb += ssb[w2]; }
        float na = sqrtf(ta), nb = sqrtf(tb);
        g_an[fb]  = na;
        g_pos[fb] = td / (fmaxf(na, EPSF) * fmaxf(nb, EPSF)) * INV_T;
    }
}

// ---------------------------------------------------------------------------
// Kernel 3: channel Gram via mma.sync (sm_100-safe tensor cores).
// 6 GEMMs: D = X[1024,512] . Y[1024,512]^T, bf16 in, fp32 out.
// grid = 6*64 CTAs of 256 threads; CTA tile 128x128, warp tile 64x32,
// K-slab 32, double-buffered smem (2 x 20KB, rows padded to 40 halves).
// ---------------------------------------------------------------------------
constexpr int APITCH = 40;                 // halves per smem row (32 + 8 pad)
constexpr int SLAB_A = 128 * APITCH * 2;   // 10240 B
constexpr int SLAB_BYTES = 2 * SLAB_A;     // 20480 B (A + B)
constexpr int GRAM_SMEM = 2 * SLAB_BYTES;  // 40960 B

__global__ void __launch_bounds__(256) k_gram_mma() {
    extern __shared__ __align__(16) char smem[];
    uint32_t sb = smem_u32(smem);
    int tid = threadIdx.x, lane = tid & 31, warp = tid >> 5;
    int wm = warp & 1, wn = warp >> 1;     // 2 x 4 warp grid

    int bid = blockIdx.x;
    int g = bid >> 6;                      // 0..5 = f*2 + type
    int mi = (bid >> 3) & 7;
    int nj = bid & 7;
    int f = g >> 1, type = g & 1;

    const __nv_bfloat16* Asrc = g_bi + (size_t)f * B * CD + (size_t)mi * 128 * 512;
    const __nv_bfloat16* Bsrc = (type ? g_bi : g_bj) + (size_t)f * B * CD + (size_t)nj * 128 * 512;

    float acc[4][4][4];
#pragma unroll
    for (int a = 0; a < 4; a++)
#pragma unroll
        for (int b = 0; b < 4; b++)
#pragma unroll
            for (int q = 0; q < 4; q++) acc[a][b][q] = 0.f;

    auto load_slab = [&](int stage, int ks) {
        char* s = smem + stage * SLAB_BYTES;
#pragma unroll
        for (int q = 0; q < 2; q++) {
            int idx = tid + q * 256;       // 0..511
            int r = idx >> 2;              // 0..127
            int kc = (idx & 3) * 8;        // 0,8,16,24 halves
            *reinterpret_cast<uint4*>(s + (r * APITCH + kc) * 2) =
                *reinterpret_cast<const uint4*>(Asrc + (size_t)r * 512 + ks + kc);
            *reinterpret_cast<uint4*>(s + SLAB_A + (r * APITCH + kc) * 2) =
                *reinterpret_cast<const uint4*>(Bsrc + (size_t)r * 512 + ks + kc);
        }
    };

    load_slab(0, 0);
    __syncthreads();

    for (int s = 0; s < 16; s++) {
        if (s < 15) load_slab((s + 1) & 1, (s + 1) * 32);

        uint32_t base = sb + (s & 1) * SLAB_BYTES;
#pragma unroll
        for (int kt = 0; kt < 2; kt++) {
            uint32_t af[4][4], bfr[2][4];
#pragma unroll
            for (int mt = 0; mt < 4; mt++) {
                int row = wm * 64 + mt * 16 + ((lane >> 3) & 1) * 8 + (lane & 7);
                int col = kt * 16 + (lane >> 4) * 8;
                ldsm4(af[mt], base + (row * APITCH + col) * 2);
            }
#pragma unroll
            for (int nt2 = 0; nt2 < 2; nt2++) {
                int nrow = wn * 32 + nt2 * 16 + (lane >> 4) * 8 + (lane & 7);
                int kcol = kt * 16 + ((lane >> 3) & 1) * 8;
                ldsm4(bfr[nt2], base + SLAB_A + (nrow * APITCH + kcol) * 2);
            }
#pragma unroll
            for (int mt = 0; mt < 4; mt++)
#pragma unroll
                for (int nt = 0; nt < 4; nt++)
                    mma16816(acc[mt][nt], af[mt],
                             bfr[nt >> 1][(nt & 1) * 2], bfr[nt >> 1][(nt & 1) * 2 + 1]);
        }
        __syncthreads();
    }

    // epilogue: write fp32 accumulators to g_gram
    float* G = g_gram + ((size_t)g << 20);
    int gq = lane >> 2, tq = lane & 3;
#pragma unroll
    for (int mt = 0; mt < 4; mt++) {
#pragma unroll
        for (int nt = 0; nt < 4; nt++) {
            int m0 = mi * 128 + wm * 64 + mt * 16 + gq;
            int n0 = nj * 128 + wn * 32 + nt * 8 + tq * 2;
            *reinterpret_cast<float2*>(G + (size_t)m0 * 1024 + n0) =
                make_float2(acc[mt][nt][0], acc[mt][nt][1]);
            *reinterpret_cast<float2*>(G + (size_t)(m0 + 8) * 1024 + n0) =
                make_float2(acc[mt][nt][2], acc[mt][nt][3]);
        }
    }
}

// ---------------------------------------------------------------------------
// Kernel 4: gathered sums over Gram -> similarity logits
// grid = 2*F*B blocks (type,f,i), 64 threads (j each)
// ---------------------------------------------------------------------------
__global__ void k_gather(const int* __restrict__ ids_raw,
                         const int* __restrict__ idxj,
                         const int* __restrict__ idxk) {
    int bid = blockIdx.x;
    int i = bid & 63;
    int f = (bid >> 6) % F;
    int type = bid / (64 * F);
    int j = threadIdx.x;

    bool is64 = (ids_raw[1] == 0) && (ids_raw[3] == 0) && (ids_raw[5] == 0) && (ids_raw[7] == 0);
    const long long* ids64 = reinterpret_cast<const long long*>(ids_raw);
    long long myid = is64 ? ids64[i] : (long long)ids_raw[i];
    long long jid  = is64 ? ids64[j] : (long long)ids_raw[j];

    float* out = g_sim + ((size_t)(type * F + f) * B + i) * B;
    if (j == i || jid == myid) { out[j] = NEGINF; return; }

    const float* G = g_gram + ((size_t)(f * 2 + type) << 20);
    const int* idx = (type ? idxk : idxj) + ((size_t)((f * B + i) * B) + j) * C;
    const float* rn = (type ? g_rni : g_rnj) + (f * B + j) * C;

    float acc = 0.f, nsq = 0.f;
#pragma unroll
    for (int c = 0; c < C; c++) {
        int cc = idx[c];
        acc += G[(size_t)(i * C + c) * 1024 + j * C + cc];
        nsq += rn[cc];
    }
    float na = fmaxf(g_an[f * B + i], EPSF);
    float nb = fmaxf(sqrtf(nsq), EPSF);
    out[j] = acc / (na * nb) * INV_T;
}

// ---------------------------------------------------------------------------
// Kernel 5: logsumexp, one WARP per (f,i) row
// ---------------------------------------------------------------------------
__global__ void k_lse() {
    int wid = threadIdx.x >> 5, lane = threadIdx.x & 31;
    int r = blockIdx.x * 32 + wid;          // 0..191
    float p = g_pos[r];
    const float* sj = g_sim + (size_t)r * B;
    const float* sk = g_sim + (size_t)F * B * B + (size_t)r * B;
    float v0 = sj[lane], v1 = sj[lane + 32], v2 = sk[lane], v3 = sk[lane + 32];
    float m = fmaxf(fmaxf(v0, v1), fmaxf(v2, v3));
    m = fmaxf(m, p);
    m = warpmax(m);
    float s = expf(v0 - m) + expf(v1 - m) + expf(v2 - m) + expf(v3 - m);
    s = warpsum(s);
    if (!lane) g_loss[r] = logf(s + expf(p - m)) + m - p;
}

// ---------------------------------------------------------------------------
// Kernel 6: final sum
// ---------------------------------------------------------------------------
__global__ void k_sum(float* __restrict__ out) {
    int t = threadIdx.x;
    float v = g_loss[t];
    v = warpsum(v);
    __shared__ float sm[6];
    if (!(t & 31)) sm[t >> 5] = v;
    __syncthreads();
    if (t == 0) {
        float tot = 0.f;
#pragma unroll
        for (int w = 0; w < 6; w++) tot += sm[w];
        out[0] = tot * (1.0f / 128.0f);   // / (2 * BATCH_SIZE)
    }
}

}  // namespace

extern "C" void kernel_launch(void* const* d_in, const int* in_sizes, int n_in,
                              void* d_out, int out_size) {
    const float* fi   = (const float*)d_in[0];
    const float* fj   = (const float*)d_in[1];
    const int*   ids  = (const int*)d_in[2];
    const int*   idxj = (const int*)d_in[3];
    const int*   idxk = (const int*)d_in[4];
    float* out = (float*)d_out;

    k_convert<<<2 * F * B * C, 128>>>(fi, fj);
    k_pos<<<F * B, 256>>>(fi, fj);
    k_gram_mma<<<6 * 64, 256, GRAM_SMEM>>>();
    k_gather<<<2 * F * B, 64>>>(ids, idxj, idxk);
    k_lse<<<F * B / 32, 1024>>>();
    k_sum<<<1, 192>>>(out);
}

// round 7
// speedup vs baseline: 2.0034x; 1.2711x over previous
#include <cuda_runtime.h>
#include <cuda_bf16.h>
#include <cstdint>
#include <math.h>

namespace {

constexpr int F = 3, B = 64, C = 16, D = 512;
constexpr int CD = C * D;                 // 8192
constexpr int BC = B * C;                 // 1024 (Gram dimension)
constexpr float EPSF = 1e-8f;
constexpr float NEGINF = -1e30f;
constexpr float INV_T = 10.0f;            // 1 / 0.1

// ---- device scratch (no allocation allowed) ----
__device__ __align__(16) __nv_bfloat16 g_bi[F * B * CD];   // bf16 fmaps_i
__device__ __align__(16) __nv_bfloat16 g_bj[F * B * CD];   // bf16 fmaps_j
__device__ float g_rni[F * B * C];        // per-channel ||.||^2 fmaps_i
__device__ float g_rnj[F * B * C];        // per-channel ||.||^2 fmaps_j
__device__ float g_an[F * B];             // anchor norms
__device__ float g_pos[F * B];            // pos_sim / T
__device__ __align__(16) float g_gram[6 * BC * BC];  // [f*2+type][1024][1024]
__device__ float g_loss[F * B];

__device__ __forceinline__ float warpsum(float v) {
#pragma unroll
    for (int o = 16; o; o >>= 1) v += __shfl_down_sync(0xffffffffu, v, o);
    return v;
}
__device__ __forceinline__ float warpmax(float v) {
#pragma unroll
    for (int o = 16; o; o >>= 1) v = fmaxf(v, __shfl_xor_sync(0xffffffffu, v, o));
    return v;
}

__device__ __forceinline__ uint32_t smem_u32(const void* p) {
    uint32_t a;
    asm("{ .reg .u64 t; cvta.to.shared.u64 t, %1; cvt.u32.u64 %0, t; }" : "=r"(a) : "l"(p));
    return a;
}
__device__ __forceinline__ void ldsm4(uint32_t* r, uint32_t addr) {
    asm volatile("ldmatrix.sync.aligned.m8n8.x4.shared.b16 {%0,%1,%2,%3}, [%4];"
        : "=r"(r[0]), "=r"(r[1]), "=r"(r[2]), "=r"(r[3]) : "r"(addr));
}
__device__ __forceinline__ void mma16816(float* c, const uint32_t* a,
                                         uint32_t b0, uint32_t b1) {
    asm volatile(
        "mma.sync.aligned.m16n8k16.row.col.f32.bf16.bf16.f32 "
        "{%0,%1,%2,%3}, {%4,%5,%6,%7}, {%8,%9}, {%0,%1,%2,%3};"
        : "+f"(c[0]), "+f"(c[1]), "+f"(c[2]), "+f"(c[3])
        : "r"(a[0]), "r"(a[1]), "r"(a[2]), "r"(a[3]), "r"(b0), "r"(b1));
}
__device__ __forceinline__ void cpasync16(uint32_t dst, const void* src) {
    asm volatile("cp.async.cg.shared.global [%0], [%1], 16;" :: "r"(dst), "l"(src));
}
#define CP_COMMIT() asm volatile("cp.async.commit_group;" ::: "memory")
#define CP_WAIT1() asm volatile("cp.async.wait_group 1;" ::: "memory")
#define CP_WAIT0() asm volatile("cp.async.wait_group 0;" ::: "memory")

// ---------------------------------------------------------------------------
// Kernel 1: fp32 -> bf16 + per-channel squared norms
// ---------------------------------------------------------------------------
__global__ void k_convert(const float* __restrict__ fi, const float* __restrict__ fj) {
    int bid = blockIdx.x;
    int half = (bid >= F * B * C) ? 1 : 0;
    int ch = half ? (bid - F * B * C) : bid;
    const float4* src = reinterpret_cast<const float4*>((half ? fj : fi) + (size_t)ch * D);
    __nv_bfloat162* dst = reinterpret_cast<__nv_bfloat162*>((half ? g_bj : g_bi) + (size_t)ch * D);
    float* rn = half ? g_rnj : g_rni;

    int t = threadIdx.x;                           // 128 threads * 4 floats = 512
    float4 v = src[t];
    dst[2 * t]     = __floats2bfloat162_rn(v.x, v.y);
    dst[2 * t + 1] = __floats2bfloat162_rn(v.z, v.w);

    float ss = v.x * v.x + v.y * v.y + v.z * v.z + v.w * v.w;
    ss = warpsum(ss);
    __shared__ float s[4];
    if ((t & 31) == 0) s[t >> 5] = ss;
    __syncthreads();
    if (t == 0) rn[ch] = s[0] + s[1] + s[2] + s[3];
}

// ---------------------------------------------------------------------------
// Kernel 2: pos_sim (full fp32) + anchor norms
// ---------------------------------------------------------------------------
__global__ void k_pos(const float* __restrict__ fi, const float* __restrict__ fj) {
    int fb = blockIdx.x;
    const float4* a = reinterpret_cast<const float4*>(fi + (size_t)fb * CD);
    const float4* p = reinterpret_cast<const float4*>(fj + (size_t)fb * CD);
    float dot = 0.f, sa = 0.f, sb = 0.f;
    for (int k = threadIdx.x; k < CD / 4; k += 256) {
        float4 x = a[k], y = p[k];
        dot += x.x * y.x + x.y * y.y + x.z * y.z + x.w * y.w;
        sa  += x.x * x.x + x.y * x.y + x.z * x.z + x.w * x.w;
        sb  += y.x * y.x + y.y * y.y + y.z * y.z + y.w * y.w;
    }
    dot = warpsum(dot); sa = warpsum(sa); sb = warpsum(sb);
    __shared__ float sd[8], ssa[8], ssb[8];
    int w = threadIdx.x >> 5, l = threadIdx.x & 31;
    if (!l) { sd[w] = dot; ssa[w] = sa; ssb[w] = sb; }
    __syncthreads();
    if (threadIdx.x == 0) {
        float td = 0.f, ta = 0.f, tb = 0.f;
#pragma unroll
        for (int w2 = 0; w2 < 8; w2++) { td += sd[w2]; ta += ssa[w2]; tb += ssb[w2]; }
        float na = sqrtf(ta), nb = sqrtf(tb);
        g_an[fb]  = na;
        g_pos[fb] = td / (fmaxf(na, EPSF) * fmaxf(nb, EPSF)) * INV_T;
    }
}

// ---------------------------------------------------------------------------
// Kernel 3: channel Gram via mma.sync, cp.async double-buffered.
// 6 GEMMs: D = X[1024,512] . Y[1024,512]^T, bf16 in, fp32 out.
// grid = 6*64 CTAs of 256 threads; CTA tile 128x128, warp tile 64x32,
// K-slab 32; __launch_bounds__(256,2) pins <=128 regs -> 2 CTAs/SM.
// ---------------------------------------------------------------------------
constexpr int APITCH = 40;                 // halves per smem row (32 + 8 pad)
constexpr int SLAB_A = 128 * APITCH * 2;   // 10240 B
constexpr int SLAB_BYTES = 2 * SLAB_A;     // 20480 B (A + B)
constexpr int GRAM_SMEM = 2 * SLAB_BYTES;  // 40960 B (2 stages)

__global__ void __launch_bounds__(256, 2) k_gram_mma() {
    extern __shared__ __align__(16) char smem[];
    uint32_t sb = smem_u32(smem);
    int tid = threadIdx.x, lane = tid & 31, warp = tid >> 5;
    int wm = warp & 1, wn = warp >> 1;     // 2 x 4 warp grid

    int bid = blockIdx.x;
    int g = bid >> 6;                      // 0..5 = f*2 + type
    int mi = (bid >> 3) & 7;
    int nj = bid & 7;
    int f = g >> 1, type = g & 1;

    const __nv_bfloat16* Asrc = g_bi + (size_t)f * B * CD + (size_t)mi * 128 * 512;
    const __nv_bfloat16* Bsrc = (type ? g_bi : g_bj) + (size_t)f * B * CD + (size_t)nj * 128 * 512;

    // per-thread copy coordinates (2 chunks of 16B for A, 2 for B per slab)
    int r0 = tid >> 2;                     // row for q=0
    int kc0 = (tid & 3) * 8;
    int r1 = (tid + 256) >> 2;
    int kc1 = kc0;                         // same (tid&3)

    auto issue_slab = [&](int stage, int ks) {
        uint32_t s = sb + stage * SLAB_BYTES;
        cpasync16(s + (r0 * APITCH + kc0) * 2, Asrc + (size_t)r0 * 512 + ks + kc0);
        cpasync16(s + SLAB_A + (r0 * APITCH + kc0) * 2, Bsrc + (size_t)r0 * 512 + ks + kc0);
        cpasync16(s + (r1 * APITCH + kc1) * 2, Asrc + (size_t)r1 * 512 + ks + kc1);
        cpasync16(s + SLAB_A + (r1 * APITCH + kc1) * 2, Bsrc + (size_t)r1 * 512 + ks + kc1);
    };

    float acc[4][4][4];
#pragma unroll
    for (int a = 0; a < 4; a++)
#pragma unroll
        for (int b = 0; b < 4; b++)
#pragma unroll
            for (int q = 0; q < 4; q++) acc[a][b][q] = 0.f;

    issue_slab(0, 0);
    CP_COMMIT();

    for (int s = 0; s < 16; s++) {
        if (s < 15) {
            issue_slab((s + 1) & 1, (s + 1) * 32);
            CP_COMMIT();
            CP_WAIT1();
        } else {
            CP_WAIT0();
        }
        __syncthreads();

        uint32_t base = sb + (s & 1) * SLAB_BYTES;
#pragma unroll
        for (int kt = 0; kt < 2; kt++) {
            uint32_t af[4][4], bfr[2][4];
#pragma unroll
            for (int mt = 0; mt < 4; mt++) {
                int row = wm * 64 + mt * 16 + ((lane >> 3) & 1) * 8 + (lane & 7);
                int col = kt * 16 + (lane >> 4) * 8;
                ldsm4(af[mt], base + (row * APITCH + col) * 2);
            }
#pragma unroll
            for (int nt2 = 0; nt2 < 2; nt2++) {
                int nrow = wn * 32 + nt2 * 16 + (lane >> 4) * 8 + (lane & 7);
                int kcol = kt * 16 + ((lane >> 3) & 1) * 8;
                ldsm4(bfr[nt2], base + SLAB_A + (nrow * APITCH + kcol) * 2);
            }
#pragma unroll
            for (int mt = 0; mt < 4; mt++)
#pragma unroll
                for (int nt = 0; nt < 4; nt++)
                    mma16816(acc[mt][nt], af[mt],
                             bfr[nt >> 1][(nt & 1) * 2], bfr[nt >> 1][(nt & 1) * 2 + 1]);
        }
        __syncthreads();
    }

    // epilogue: write fp32 accumulators to g_gram
    float* G = g_gram + ((size_t)g << 20);
    int gq = lane >> 2, tq = lane & 3;
#pragma unroll
    for (int mt = 0; mt < 4; mt++) {
#pragma unroll
        for (int nt = 0; nt < 4; nt++) {
            int m0 = mi * 128 + wm * 64 + mt * 16 + gq;
            int n0 = nj * 128 + wn * 32 + nt * 8 + tq * 2;
            *reinterpret_cast<float2*>(G + (size_t)m0 * 1024 + n0) =
                make_float2(acc[mt][nt][0], acc[mt][nt][1]);
            *reinterpret_cast<float2*>(G + (size_t)(m0 + 8) * 1024 + n0) =
                make_float2(acc[mt][nt][2], acc[mt][nt][3]);
        }
    }
}

// ---------------------------------------------------------------------------
// Kernel 4: fused gather + logsumexp. grid = F*B blocks (f,i), 256 threads.
// thread = type(1b) | j(6b) | half(1b): 8 gathered Gram loads each,
// pair-combined via shfl_xor(1); then block-wide logsumexp -> g_loss.
// NOTE: gather + shfl run UNCONDITIONALLY (all loads in-bounds); the
// neg-mask selects NEGINF afterwards. A sync-shfl inside the divergent
// branch deadlocked in R6.
// ---------------------------------------------------------------------------
__global__ void __launch_bounds__(256) k_negls(const int* __restrict__ ids_raw,
                                               const int* __restrict__ idxj,
                                               const int* __restrict__ idxk) {
    int fb = blockIdx.x;                  // f*B + i
    int f = fb >> 6, i = fb & 63;
    int tid = threadIdx.x;
    int half = tid & 1;
    int j = (tid >> 1) & 63;
    int type = tid >> 7;

    __shared__ float slog[132];           // [0]=pos, [1..128] logits
    __shared__ float smax[8], ssum[8];

    bool is64 = (ids_raw[1] == 0) && (ids_raw[3] == 0) && (ids_raw[5] == 0) && (ids_raw[7] == 0);
    const long long* ids64 = reinterpret_cast<const long long*>(ids_raw);
    long long myid = is64 ? ids64[i] : (long long)ids_raw[i];
    long long jid  = is64 ? ids64[j] : (long long)ids_raw[j];

    const float* G = g_gram + ((size_t)(f * 2 + type) << 20);
    const int* idx = (type ? idxk : idxj) + ((size_t)(fb * B) + j) * C + half * 8;
    const float* rn = (type ? g_rni : g_rnj) + (f * B + j) * C;

    float acc = 0.f, nsq = 0.f;
#pragma unroll
    for (int c = 0; c < 8; c++) {
        int cc = idx[c];
        acc += G[(size_t)(i * C + half * 8 + c) * 1024 + j * C + cc];
        nsq += rn[cc];
    }
    acc += __shfl_xor_sync(0xffffffffu, acc, 1);
    nsq += __shfl_xor_sync(0xffffffffu, nsq, 1);
    float na = fmaxf(g_an[fb], EPSF);
    float nb = fmaxf(sqrtf(nsq), EPSF);
    bool valid = (j != i) && (jid != myid);
    float val = valid ? (acc / (na * nb) * INV_T) : NEGINF;

    if (half == 0) slog[1 + type * 64 + j] = val;
    if (tid == 0) slog[0] = g_pos[fb];
    __syncthreads();

    // block logsumexp over slog[0..128]
    float x = (tid < 129) ? slog[tid] : NEGINF;
    float m = warpmax(x);
    int w = tid >> 5, l = tid & 31;
    if (!l) smax[w] = m;
    __syncthreads();
    float bm = fmaxf(fmaxf(fmaxf(smax[0], smax[1]), fmaxf(smax[2], smax[3])),
                     fmaxf(fmaxf(smax[4], smax[5]), fmaxf(smax[6], smax[7])));
    float e = (tid < 129) ? expf(x - bm) : 0.f;
    e = warpsum(e);
    if (!l) ssum[w] = e;
    __syncthreads();
    if (tid == 0) {
        float s = ssum[0] + ssum[1] + ssum[2] + ssum[3]
                + ssum[4] + ssum[5] + ssum[6] + ssum[7];
        g_loss[fb] = logf(s) + bm - slog[0];
    }
}

// ---------------------------------------------------------------------------
// Kernel 5: final sum
// ---------------------------------------------------------------------------
__global__ void k_sum(float* __restrict__ out) {
    int t = threadIdx.x;
    float v = g_loss[t];
    v = warpsum(v);
    __shared__ float sm[6];
    if (!(t & 31)) sm[t >> 5] = v;
    __syncthreads();
    if (t == 0) {
        float tot = 0.f;
#pragma unroll
        for (int w = 0; w < 6; w++) tot += sm[w];
        out[0] = tot * (1.0f / 128.0f);   // / (2 * BATCH_SIZE)
    }
}

}  // namespace

extern "C" void kernel_launch(void* const* d_in, const int* in_sizes, int n_in,
                              void* d_out, int out_size) {
    const float* fi   = (const float*)d_in[0];
    const float* fj   = (const float*)d_in[1];
    const int*   ids  = (const int*)d_in[2];
    const int*   idxj = (const int*)d_in[3];
    const int*   idxk = (const int*)d_in[4];
    float* out = (float*)d_out;

    k_convert<<<2 * F * B * C, 128>>>(fi, fj);
    k_pos<<<F * B, 256>>>(fi, fj);
    k_gram_mma<<<6 * 64, 256, GRAM_SMEM>>>();
    k_negls<<<F * B, 256>>>(ids, idxj, idxk);
    k_sum<<<1, 192>>>(out);
}

// round 8
// speedup vs baseline: 2.2024x; 1.0993x over previous
#include <cuda_runtime.h>
#include <cuda_bf16.h>
#include <cstdint>
#include <math.h>

namespace {

constexpr int F = 3, B = 64, C = 16, D = 512;
constexpr int CD = C * D;                 // 8192
constexpr int BC = B * C;                 // 1024 (Gram dimension)
constexpr float EPSF = 1e-8f;
constexpr float NEGINF = -1e30f;
constexpr float INV_T = 10.0f;            // 1 / 0.1

// ---- device scratch (no allocation allowed) ----
__device__ __align__(16) __nv_bfloat16 g_bi[F * B * CD];   // bf16 fmaps_i
__device__ __align__(16) __nv_bfloat16 g_bj[F * B * CD];   // bf16 fmaps_j
__device__ float g_rni[F * B * C];        // per-channel ||.||^2 fmaps_i
__device__ float g_rnj[F * B * C];        // per-channel ||.||^2 fmaps_j
__device__ float g_an[F * B];             // anchor norms
__device__ float g_pos[F * B];            // pos_sim / T
__device__ __align__(16) float g_gram[6 * BC * BC];  // [f*2+type][1024][1024]
__device__ float g_loss[F * B];

__device__ __forceinline__ float warpsum(float v) {
#pragma unroll
    for (int o = 16; o; o >>= 1) v += __shfl_down_sync(0xffffffffu, v, o);
    return v;
}
__device__ __forceinline__ float warpmax(float v) {
#pragma unroll
    for (int o = 16; o; o >>= 1) v = fmaxf(v, __shfl_xor_sync(0xffffffffu, v, o));
    return v;
}

__device__ __forceinline__ uint32_t smem_u32(const void* p) {
    uint32_t a;
    asm("{ .reg .u64 t; cvta.to.shared.u64 t, %1; cvt.u32.u64 %0, t; }" : "=r"(a) : "l"(p));
    return a;
}
__device__ __forceinline__ void ldsm4(uint32_t* r, uint32_t addr) {
    asm volatile("ldmatrix.sync.aligned.m8n8.x4.shared.b16 {%0,%1,%2,%3}, [%4];"
        : "=r"(r[0]), "=r"(r[1]), "=r"(r[2]), "=r"(r[3]) : "r"(addr));
}
__device__ __forceinline__ void mma16816(float* c, const uint32_t* a,
                                         uint32_t b0, uint32_t b1) {
    asm volatile(
        "mma.sync.aligned.m16n8k16.row.col.f32.bf16.bf16.f32 "
        "{%0,%1,%2,%3}, {%4,%5,%6,%7}, {%8,%9}, {%0,%1,%2,%3};"
        : "+f"(c[0]), "+f"(c[1]), "+f"(c[2]), "+f"(c[3])
        : "r"(a[0]), "r"(a[1]), "r"(a[2]), "r"(a[3]), "r"(b0), "r"(b1));
}
__device__ __forceinline__ void cpasync16(uint32_t dst, const void* src) {
    asm volatile("cp.async.cg.shared.global [%0], [%1], 16;" :: "r"(dst), "l"(src));
}
#define CP_COMMIT() asm volatile("cp.async.commit_group;" ::: "memory")
#define CP_WAIT3() asm volatile("cp.async.wait_group 3;" ::: "memory")

// ---------------------------------------------------------------------------
// Kernel 1: fused prep — one pass over fp32 inputs.
// grid = F*B blocks of 256 threads (8 warps). Warp w handles channels w, w+8.
// Produces: bf16 copies, per-channel sq norms, row norms, pos_sim.
// ---------------------------------------------------------------------------
__global__ void __launch_bounds__(256) k_prep(const float* __restrict__ fi,
                                              const float* __restrict__ fj) {
    int fb = blockIdx.x;
    int t = threadIdx.x, w = t >> 5, lane = t & 31;
    const float4* ai = reinterpret_cast<const float4*>(fi + (size_t)fb * CD);
    const float4* aj = reinterpret_cast<const float4*>(fj + (size_t)fb * CD);
    __nv_bfloat162* bi = reinterpret_cast<__nv_bfloat162*>(g_bi + (size_t)fb * CD);
    __nv_bfloat162* bj = reinterpret_cast<__nv_bfloat162*>(g_bj + (size_t)fb * CD);

    __shared__ float sni[C], snj[C], sdot[8];

    float dot = 0.f;
#pragma unroll
    for (int rep = 0; rep < 2; rep++) {
        int ch = w + rep * 8;
        float ssi = 0.f, ssj = 0.f;
#pragma unroll
        for (int q = 0; q < 4; q++) {
            int k = ch * 128 + q * 32 + lane;       // float4 index
            float4 vi = ai[k], vj = aj[k];
            ssi += vi.x * vi.x + vi.y * vi.y + vi.z * vi.z + vi.w * vi.w;
            ssj += vj.x * vj.x + vj.y * vj.y + vj.z * vj.z + vj.w * vj.w;
            dot += vi.x * vj.x + vi.y * vj.y + vi.z * vj.z + vi.w * vj.w;
            bi[2 * k]     = __floats2bfloat162_rn(vi.x, vi.y);
            bi[2 * k + 1] = __floats2bfloat162_rn(vi.z, vi.w);
            bj[2 * k]     = __floats2bfloat162_rn(vj.x, vj.y);
            bj[2 * k + 1] = __floats2bfloat162_rn(vj.z, vj.w);
        }
        ssi = warpsum(ssi);
        ssj = warpsum(ssj);
        if (!lane) {
            g_rni[fb * C + ch] = ssi;
            g_rnj[fb * C + ch] = ssj;
            sni[ch] = ssi;
            snj[ch] = ssj;
        }
    }
    dot = warpsum(dot);
    if (!lane) sdot[w] = dot;
    __syncthreads();
    if (t == 0) {
        float na2 = 0.f, nb2 = 0.f, td = 0.f;
#pragma unroll
        for (int c = 0; c < C; c++) { na2 += sni[c]; nb2 += snj[c]; }
#pragma unroll
        for (int w2 = 0; w2 < 8; w2++) td += sdot[w2];
        float na = sqrtf(na2), nb = sqrtf(nb2);
        g_an[fb]  = na;
        g_pos[fb] = td / (fmaxf(na, EPSF) * fmaxf(nb, EPSF)) * INV_T;
    }
}

// ---------------------------------------------------------------------------
// Kernel 2: channel Gram via mma.sync, 4-stage cp.async pipeline.
// 6 GEMMs: D = X[1024,512] . Y[1024,512]^T, bf16 in, fp32 out.
// grid = 6*64 CTAs of 256 threads; CTA tile 128x128, warp tile 64x32,
// K-slab 32; __launch_bounds__(256,2) -> 2 CTAs/SM (2 x 80KB smem fits).
// ---------------------------------------------------------------------------
constexpr int APITCH = 40;                 // halves per smem row (32 + 8 pad)
constexpr int SLAB_A = 128 * APITCH * 2;   // 10240 B
constexpr int SLAB_BYTES = 2 * SLAB_A;     // 20480 B (A + B)
constexpr int STAGES = 4;
constexpr int GRAM_SMEM = STAGES * SLAB_BYTES;  // 81920 B

__global__ void __launch_bounds__(256, 2) k_gram_mma() {
    extern __shared__ __align__(16) char smem[];
    uint32_t sb = smem_u32(smem);
    int tid = threadIdx.x, lane = tid & 31, warp = tid >> 5;
    int wm = warp & 1, wn = warp >> 1;     // 2 x 4 warp grid

    int bid = blockIdx.x;
    int g = bid >> 6;                      // 0..5 = f*2 + type
    int mi = (bid >> 3) & 7;
    int nj = bid & 7;
    int f = g >> 1, type = g & 1;

    const __nv_bfloat16* Asrc = g_bi + (size_t)f * B * CD + (size_t)mi * 128 * 512;
    const __nv_bfloat16* Bsrc = (type ? g_bi : g_bj) + (size_t)f * B * CD + (size_t)nj * 128 * 512;

    int r0 = tid >> 2;
    int kc0 = (tid & 3) * 8;
    int r1 = (tid + 256) >> 2;

    auto issue_slab = [&](int stage, int ks) {
        uint32_t s = sb + stage * SLAB_BYTES;
        cpasync16(s + (r0 * APITCH + kc0) * 2, Asrc + (size_t)r0 * 512 + ks + kc0);
        cpasync16(s + SLAB_A + (r0 * APITCH + kc0) * 2, Bsrc + (size_t)r0 * 512 + ks + kc0);
        cpasync16(s + (r1 * APITCH + kc0) * 2, Asrc + (size_t)r1 * 512 + ks + kc0);
        cpasync16(s + SLAB_A + (r1 * APITCH + kc0) * 2, Bsrc + (size_t)r1 * 512 + ks + kc0);
    };

    float acc[4][4][4];
#pragma unroll
    for (int a = 0; a < 4; a++)
#pragma unroll
        for (int b = 0; b < 4; b++)
#pragma unroll
            for (int q = 0; q < 4; q++) acc[a][b][q] = 0.f;

    // prologue: prefetch 3 slabs
#pragma unroll
    for (int p = 0; p < 3; p++) {
        issue_slab(p, p * 32);
        CP_COMMIT();
    }

    for (int s = 0; s < 16; s++) {
        if (s + 3 < 16) issue_slab((s + 3) & 3, (s + 3) * 32);
        CP_COMMIT();                       // (possibly empty group; keeps count uniform)
        CP_WAIT3();                        // slab s guaranteed complete
        __syncthreads();

        uint32_t base = sb + (s & 3) * SLAB_BYTES;
#pragma unroll
        for (int kt = 0; kt < 2; kt++) {
            uint32_t af[4][4], bfr[2][4];
#pragma unroll
            for (int mt = 0; mt < 4; mt++) {
                int row = wm * 64 + mt * 16 + ((lane >> 3) & 1) * 8 + (lane & 7);
                int col = kt * 16 + (lane >> 4) * 8;
                ldsm4(af[mt], base + (row * APITCH + col) * 2);
            }
#pragma unroll
            for (int nt2 = 0; nt2 < 2; nt2++) {
                int nrow = wn * 32 + nt2 * 16 + (lane >> 4) * 8 + (lane & 7);
                int kcol = kt * 16 + ((lane >> 3) & 1) * 8;
                ldsm4(bfr[nt2], base + SLAB_A + (nrow * APITCH + kcol) * 2);
            }
#pragma unroll
            for (int mt = 0; mt < 4; mt++)
#pragma unroll
                for (int nt = 0; nt < 4; nt++)
                    mma16816(acc[mt][nt], af[mt],
                             bfr[nt >> 1][(nt & 1) * 2], bfr[nt >> 1][(nt & 1) * 2 + 1]);
        }
        __syncthreads();
    }

    // epilogue: write fp32 accumulators to g_gram
    float* G = g_gram + ((size_t)g << 20);
    int gq = lane >> 2, tq = lane & 3;
#pragma unroll
    for (int mt = 0; mt < 4; mt++) {
#pragma unroll
        for (int nt = 0; nt < 4; nt++) {
            int m0 = mi * 128 + wm * 64 + mt * 16 + gq;
            int n0 = nj * 128 + wn * 32 + nt * 8 + tq * 2;
            *reinterpret_cast<float2*>(G + (size_t)m0 * 1024 + n0) =
                make_float2(acc[mt][nt][0], acc[mt][nt][1]);
            *reinterpret_cast<float2*>(G + (size_t)(m0 + 8) * 1024 + n0) =
                make_float2(acc[mt][nt][2], acc[mt][nt][3]);
        }
    }
}

// ---------------------------------------------------------------------------
// Kernel 3: fused gather + logsumexp. grid = F*B blocks (f,i), 512 threads.
// thread = type(1b) | j(6b) | quarter(2b): 4 gathered Gram loads each,
// quarter-combined via shfl_xor(1,2); then block-wide logsumexp -> g_loss.
// Gather + shfl run unconditionally; neg-mask selects NEGINF afterwards.
// ---------------------------------------------------------------------------
__global__ void __launch_bounds__(512) k_negls(const int* __restrict__ ids_raw,
                                               const int* __restrict__ idxj,
                                               const int* __restrict__ idxk) {
    int fb = blockIdx.x;                  // f*B + i
    int f = fb >> 6, i = fb & 63;
    int tid = threadIdx.x;
    int quarter = tid & 3;
    int j = (tid >> 2) & 63;
    int type = tid >> 8;

    __shared__ float slog[132];           // [0]=pos, [1..128] logits
    __shared__ float smax[16], ssum[16];

    bool is64 = (ids_raw[1] == 0) && (ids_raw[3] == 0) && (ids_raw[5] == 0) && (ids_raw[7] == 0);
    const long long* ids64 = reinterpret_cast<const long long*>(ids_raw);
    long long myid = is64 ? ids64[i] : (long long)ids_raw[i];
    long long jid  = is64 ? ids64[j] : (long long)ids_raw[j];

    const float* G = g_gram + ((size_t)(f * 2 + type) << 20);
    const int* idxp = (type ? idxk : idxj) + ((size_t)(fb * B) + j) * C + quarter * 4;
    const float* rn = (type ? g_rni : g_rnj) + (f * B + j) * C;

    int4 cc4 = *reinterpret_cast<const int4*>(idxp);
    const float* Grow = G + (size_t)(i * C + quarter * 4) * 1024 + j * C;
    float a0 = Grow[cc4.x];
    float a1 = Grow[1024 + cc4.y];
    float a2 = Grow[2048 + cc4.z];
    float a3 = Grow[3072 + cc4.w];
    float n0 = rn[cc4.x], n1 = rn[cc4.y], n2 = rn[cc4.z], n3 = rn[cc4.w];
    float acc = (a0 + a1) + (a2 + a3);
    float nsq = (n0 + n1) + (n2 + n3);

    acc += __shfl_xor_sync(0xffffffffu, acc, 1);
    nsq += __shfl_xor_sync(0xffffffffu, nsq, 1);
    acc += __shfl_xor_sync(0xffffffffu, acc, 2);
    nsq += __shfl_xor_sync(0xffffffffu, nsq, 2);

    float na = fmaxf(g_an[fb], EPSF);
    float nb = fmaxf(sqrtf(nsq), EPSF);
    bool valid = (j != i) && (jid != myid);
    float val = valid ? (acc / (na * nb) * INV_T) : NEGINF;

    if (quarter == 0) slog[1 + type * 64 + j] = val;
    if (tid == 0) slog[0] = g_pos[fb];
    __syncthreads();

    // block logsumexp over slog[0..128]
    float x = (tid < 129) ? slog[tid] : NEGINF;
    float m = warpmax(x);
    int w = tid >> 5, l = tid & 31;
    if (!l) smax[w] = m;
    __syncthreads();
    float bm = NEGINF;
#pragma unroll
    for (int w2 = 0; w2 < 16; w2++) bm = fmaxf(bm, smax[w2]);
    float e = (tid < 129) ? expf(x - bm) : 0.f;
    e = warpsum(e);
    if (!l) ssum[w] = e;
    __syncthreads();
    if (tid == 0) {
        float s = 0.f;
#pragma unroll
        for (int w2 = 0; w2 < 16; w2++) s += ssum[w2];
        g_loss[fb] = logf(s) + bm - slog[0];
    }
}

// ---------------------------------------------------------------------------
// Kernel 4: final sum
// ---------------------------------------------------------------------------
__global__ void k_sum(float* __restrict__ out) {
    int t = threadIdx.x;
    float v = g_loss[t];
    v = warpsum(v);
    __shared__ float sm[6];
    if (!(t & 31)) sm[t >> 5] = v;
    __syncthreads();
    if (t == 0) {
        float tot = 0.f;
#pragma unroll
        for (int w = 0; w < 6; w++) tot += sm[w];
        out[0] = tot * (1.0f / 128.0f);   // / (2 * BATCH_SIZE)
    }
}

}  // namespace

extern "C" void kernel_launch(void* const* d_in, const int* in_sizes, int n_in,
                              void* d_out, int out_size) {
    const float* fi   = (const float*)d_in[0];
    const float* fj   = (const float*)d_in[1];
    const int*   ids  = (const int*)d_in[2];
    const int*   idxj = (const int*)d_in[3];
    const int*   idxk = (const int*)d_in[4];
    float* out = (float*)d_out;

    static bool attr_done = false;
    if (!attr_done) {
        cudaFuncSetAttribute(k_gram_mma, cudaFuncAttributeMaxDynamicSharedMemorySize,
                             GRAM_SMEM);
        attr_done = true;
    }

    k_prep<<<F * B, 256>>>(fi, fj);
    k_gram_mma<<<6 * 64, 256, GRAM_SMEM>>>();
    k_negls<<<F * B, 512>>>(ids, idxj, idxk);
    k_sum<<<1, 192>>>(out);
}

// round 9
// speedup vs baseline: 2.3302x; 1.0580x over previous
#include <cuda_runtime.h>
#include <cuda_bf16.h>
#include <cstdint>
#include <math.h>

namespace {

constexpr int F = 3, B = 64, C = 16, D = 512;
constexpr int CD = C * D;                 // 8192
constexpr int BC = B * C;                 // 1024 (Gram dimension)
constexpr float EPSF = 1e-8f;
constexpr float NEGINF = -1e30f;
constexpr float INV_T = 10.0f;            // 1 / 0.1

// ---- device scratch (no allocation allowed) ----
__device__ __align__(16) __nv_bfloat16 g_bi[F * B * CD];   // bf16 fmaps_i
__device__ __align__(16) __nv_bfloat16 g_bj[F * B * CD];   // bf16 fmaps_j
__device__ float g_rni[F * B * C];        // per-channel ||.||^2 fmaps_i
__device__ float g_rnj[F * B * C];        // per-channel ||.||^2 fmaps_j
__device__ float g_an[F * B];             // anchor norms
__device__ float g_pos[F * B];            // pos_sim / T
__device__ __align__(16) float g_gram[6 * BC * BC];  // [f*2+type][1024][1024]
__device__ float g_loss[F * B];
__device__ int   g_done;                  // last-block counter (reset by k_prep)

__device__ __forceinline__ float warpsum(float v) {
#pragma unroll
    for (int o = 16; o; o >>= 1) v += __shfl_down_sync(0xffffffffu, v, o);
    return v;
}
__device__ __forceinline__ float warpmax(float v) {
#pragma unroll
    for (int o = 16; o; o >>= 1) v = fmaxf(v, __shfl_xor_sync(0xffffffffu, v, o));
    return v;
}

__device__ __forceinline__ uint32_t smem_u32(const void* p) {
    uint32_t a;
    asm("{ .reg .u64 t; cvta.to.shared.u64 t, %1; cvt.u32.u64 %0, t; }" : "=r"(a) : "l"(p));
    return a;
}
__device__ __forceinline__ void ldsm4(uint32_t* r, uint32_t addr) {
    asm volatile("ldmatrix.sync.aligned.m8n8.x4.shared.b16 {%0,%1,%2,%3}, [%4];"
        : "=r"(r[0]), "=r"(r[1]), "=r"(r[2]), "=r"(r[3]) : "r"(addr));
}
__device__ __forceinline__ void mma16816(float* c, const uint32_t* a,
                                         uint32_t b0, uint32_t b1) {
    asm volatile(
        "mma.sync.aligned.m16n8k16.row.col.f32.bf16.bf16.f32 "
        "{%0,%1,%2,%3}, {%4,%5,%6,%7}, {%8,%9}, {%0,%1,%2,%3};"
        : "+f"(c[0]), "+f"(c[1]), "+f"(c[2]), "+f"(c[3])
        : "r"(a[0]), "r"(a[1]), "r"(a[2]), "r"(a[3]), "r"(b0), "r"(b1));
}
__device__ __forceinline__ void cpasync16(uint32_t dst, const void* src) {
    asm volatile("cp.async.cg.shared.global [%0], [%1], 16;" :: "r"(dst), "l"(src));
}
#define CP_COMMIT() asm volatile("cp.async.commit_group;" ::: "memory")
#define CP_WAIT1() asm volatile("cp.async.wait_group 1;" ::: "memory")

// ---------------------------------------------------------------------------
// Kernel 1: fused prep — one pass over fp32 inputs.
// grid = F*B blocks of 256 threads. Produces bf16 copies, channel norms,
// row norms, pos_sim; resets the last-block counter.
// ---------------------------------------------------------------------------
__global__ void __launch_bounds__(256) k_prep(const float* __restrict__ fi,
                                              const float* __restrict__ fj) {
    int fb = blockIdx.x;
    int t = threadIdx.x, w = t >> 5, lane = t & 31;
    if (fb == 0 && t == 0) g_done = 0;
    const float4* ai = reinterpret_cast<const float4*>(fi + (size_t)fb * CD);
    const float4* aj = reinterpret_cast<const float4*>(fj + (size_t)fb * CD);
    __nv_bfloat162* bi = reinterpret_cast<__nv_bfloat162*>(g_bi + (size_t)fb * CD);
    __nv_bfloat162* bj = reinterpret_cast<__nv_bfloat162*>(g_bj + (size_t)fb * CD);

    __shared__ float sni[C], snj[C], sdot[8];

    float dot = 0.f;
#pragma unroll
    for (int rep = 0; rep < 2; rep++) {
        int ch = w + rep * 8;
        float ssi = 0.f, ssj = 0.f;
#pragma unroll
        for (int q = 0; q < 4; q++) {
            int k = ch * 128 + q * 32 + lane;       // float4 index
            float4 vi = ai[k], vj = aj[k];
            ssi += vi.x * vi.x + vi.y * vi.y + vi.z * vi.z + vi.w * vi.w;
            ssj += vj.x * vj.x + vj.y * vj.y + vj.z * vj.z + vj.w * vj.w;
            dot += vi.x * vj.x + vi.y * vj.y + vi.z * vj.z + vi.w * vj.w;
            bi[2 * k]     = __floats2bfloat162_rn(vi.x, vi.y);
            bi[2 * k + 1] = __floats2bfloat162_rn(vi.z, vi.w);
            bj[2 * k]     = __floats2bfloat162_rn(vj.x, vj.y);
            bj[2 * k + 1] = __floats2bfloat162_rn(vj.z, vj.w);
        }
        ssi = warpsum(ssi);
        ssj = warpsum(ssj);
        if (!lane) {
            g_rni[fb * C + ch] = ssi;
            g_rnj[fb * C + ch] = ssj;
            sni[ch] = ssi;
            snj[ch] = ssj;
        }
    }
    dot = warpsum(dot);
    if (!lane) sdot[w] = dot;
    __syncthreads();
    if (t == 0) {
        float na2 = 0.f, nb2 = 0.f, td = 0.f;
#pragma unroll
        for (int c = 0; c < C; c++) { na2 += sni[c]; nb2 += snj[c]; }
#pragma unroll
        for (int w2 = 0; w2 < 8; w2++) td += sdot[w2];
        float na = sqrtf(na2), nb = sqrtf(nb2);
        g_an[fb]  = na;
        g_pos[fb] = td / (fmaxf(na, EPSF) * fmaxf(nb, EPSF)) * INV_T;
    }
}

// ---------------------------------------------------------------------------
// Kernel 2: channel Gram via mma.sync, 3-stage cp.async pipeline, K-slab 64.
// 6 GEMMs: D = X[1024,512] . Y[1024,512]^T, bf16 in, fp32 out.
// grid = 6*64 CTAs of 256 threads; CTA tile 128x128, warp tile 64x32.
// ONE __syncthreads per slab (8 slabs); prefetch depth 2 slabs.
// ---------------------------------------------------------------------------
constexpr int KSLAB = 64;
constexpr int PITCH = 72;                    // halves per smem row (64 + 8 pad)
constexpr int TILE_BYTES = 128 * PITCH * 2;  // 18432 B (one 128x64 tile)
constexpr int STAGE_BYTES = 2 * TILE_BYTES;  // 36864 B (A + B)
constexpr int STAGES = 3;
constexpr int GRAM_SMEM = STAGES * STAGE_BYTES;  // 110592 B

__global__ void __launch_bounds__(256, 2) k_gram_mma() {
    extern __shared__ __align__(16) char smem[];
    uint32_t sb = smem_u32(smem);
    int tid = threadIdx.x, lane = tid & 31, warp = tid >> 5;
    int wm = warp & 1, wn = warp >> 1;     // 2 x 4 warp grid

    int bid = blockIdx.x;
    int g = bid >> 6;                      // 0..5 = f*2 + type
    int mi = (bid >> 3) & 7;
    int nj = bid & 7;
    int f = g >> 1, type = g & 1;

    const __nv_bfloat16* Asrc = g_bi + (size_t)f * B * CD + (size_t)mi * 128 * 512;
    const __nv_bfloat16* Bsrc = (type ? g_bi : g_bj) + (size_t)f * B * CD + (size_t)nj * 128 * 512;

    // 4 A chunks + 4 B chunks of 16B per thread per slab (128 rows x 64 halves)
    auto issue_slab = [&](int stage, int ks) {
        uint32_t s = sb + stage * STAGE_BYTES;
#pragma unroll
        for (int q = 0; q < 4; q++) {
            int idx = tid + q * 256;           // 0..1023
            int r = idx >> 3;                  // row 0..127
            int kc = (idx & 7) * 8;            // col halves 0..56
            cpasync16(s + (r * PITCH + kc) * 2, Asrc + (size_t)r * 512 + ks + kc);
            cpasync16(s + TILE_BYTES + (r * PITCH + kc) * 2,
                      Bsrc + (size_t)r * 512 + ks + kc);
        }
    };

    float acc[4][4][4];
#pragma unroll
    for (int a = 0; a < 4; a++)
#pragma unroll
        for (int b = 0; b < 4; b++)
#pragma unroll
            for (int q = 0; q < 4; q++) acc[a][b][q] = 0.f;

    issue_slab(0, 0);
    CP_COMMIT();
    issue_slab(1, KSLAB);
    CP_COMMIT();

    for (int s = 0; s < 8; s++) {
        CP_WAIT1();                        // own copies for slab s complete
        __syncthreads();                   // everyone waited + prior compute done
        if (s + 2 < 8) issue_slab((s + 2) % 3, (s + 2) * KSLAB);
        CP_COMMIT();                       // uniform group count (may be empty)

        uint32_t base = sb + (s % 3) * STAGE_BYTES;
#pragma unroll
        for (int kt = 0; kt < 4; kt++) {
            uint32_t af[4][4], bfr[2][4];
#pragma unroll
            for (int mt = 0; mt < 4; mt++) {
                int row = wm * 64 + mt * 16 + ((lane >> 3) & 1) * 8 + (lane & 7);
                int col = kt * 16 + (lane >> 4) * 8;
                ldsm4(af[mt], base + (row * PITCH + col) * 2);
            }
#pragma unroll
            for (int nt2 = 0; nt2 < 2; nt2++) {
                int nrow = wn * 32 + nt2 * 16 + (lane >> 4) * 8 + (lane & 7);
                int kcol = kt * 16 + ((lane >> 3) & 1) * 8;
                ldsm4(bfr[nt2], base + TILE_BYTES + (nrow * PITCH + kcol) * 2);
            }
#pragma unroll
            for (int mt = 0; mt < 4; mt++)
#pragma unroll
                for (int nt = 0; nt < 4; nt++)
                    mma16816(acc[mt][nt], af[mt],
                             bfr[nt >> 1][(nt & 1) * 2], bfr[nt >> 1][(nt & 1) * 2 + 1]);
        }
    }

    // epilogue: write fp32 accumulators to g_gram
    float* G = g_gram + ((size_t)g << 20);
    int gq = lane >> 2, tq = lane & 3;
#pragma unroll
    for (int mt = 0; mt < 4; mt++) {
#pragma unroll
        for (int nt = 0; nt < 4; nt++) {
            int m0 = mi * 128 + wm * 64 + mt * 16 + gq;
            int n0 = nj * 128 + wn * 32 + nt * 8 + tq * 2;
            *reinterpret_cast<float2*>(G + (size_t)m0 * 1024 + n0) =
                make_float2(acc[mt][nt][0], acc[mt][nt][1]);
            *reinterpret_cast<float2*>(G + (size_t)(m0 + 8) * 1024 + n0) =
                make_float2(acc[mt][nt][2], acc[mt][nt][3]);
        }
    }
}

// ---------------------------------------------------------------------------
// Kernel 3: fused gather + logsumexp + final sum (last-block pattern).
// grid = F*B blocks (f,i), 512 threads; thread = type|j|quarter.
// Gather + shfl run unconditionally; neg-mask selects NEGINF afterwards.
// The last block to finish reduces g_loss[0..191] into out[0].
// ---------------------------------------------------------------------------
__global__ void __launch_bounds__(512) k_negls(const int* __restrict__ ids_raw,
                                               const int* __restrict__ idxj,
                                               const int* __restrict__ idxk,
                                               float* __restrict__ out) {
    int fb = blockIdx.x;                  // f*B + i
    int f = fb >> 6, i = fb & 63;
    int tid = threadIdx.x;
    int quarter = tid & 3;
    int j = (tid >> 2) & 63;
    int type = tid >> 8;

    __shared__ float slog[132];           // [0]=pos, [1..128] logits
    __shared__ float smax[16], ssum[16];
    __shared__ int s_last;

    bool is64 = (ids_raw[1] == 0) && (ids_raw[3] == 0) && (ids_raw[5] == 0) && (ids_raw[7] == 0);
    const long long* ids64 = reinterpret_cast<const long long*>(ids_raw);
    long long myid = is64 ? ids64[i] : (long long)ids_raw[i];
    long long jid  = is64 ? ids64[j] : (long long)ids_raw[j];

    const float* G = g_gram + ((size_t)(f * 2 + type) << 20);
    const int* idxp = (type ? idxk : idxj) + ((size_t)(fb * B) + j) * C + quarter * 4;
    const float* rn = (type ? g_rni : g_rnj) + (f * B + j) * C;

    int4 cc4 = *reinterpret_cast<const int4*>(idxp);
    const float* Grow = G + (size_t)(i * C + quarter * 4) * 1024 + j * C;
    float a0 = Grow[cc4.x];
    float a1 = Grow[1024 + cc4.y];
    float a2 = Grow[2048 + cc4.z];
    float a3 = Grow[3072 + cc4.w];
    float n0 = rn[cc4.x], n1 = rn[cc4.y], n2 = rn[cc4.z], n3 = rn[cc4.w];
    float acc = (a0 + a1) + (a2 + a3);
    float nsq = (n0 + n1) + (n2 + n3);

    acc += __shfl_xor_sync(0xffffffffu, acc, 1);
    nsq += __shfl_xor_sync(0xffffffffu, nsq, 1);
    acc += __shfl_xor_sync(0xffffffffu, acc, 2);
    nsq += __shfl_xor_sync(0xffffffffu, nsq, 2);

    float na = fmaxf(g_an[fb], EPSF);
    float nb = fmaxf(sqrtf(nsq), EPSF);
    bool valid = (j != i) && (jid != myid);
    float val = valid ? (acc / (na * nb) * INV_T) : NEGINF;

    if (quarter == 0) slog[1 + type * 64 + j] = val;
    if (tid == 0) slog[0] = g_pos[fb];
    __syncthreads();

    // block logsumexp over slog[0..128]
    float x = (tid < 129) ? slog[tid] : NEGINF;
    float m = warpmax(x);
    int w = tid >> 5, l = tid & 31;
    if (!l) smax[w] = m;
    __syncthreads();
    float bm = NEGINF;
#pragma unroll
    for (int w2 = 0; w2 < 16; w2++) bm = fmaxf(bm, smax[w2]);
    float e = (tid < 129) ? expf(x - bm) : 0.f;
    e = warpsum(e);
    if (!l) ssum[w] = e;
    __syncthreads();
    if (tid == 0) {
        float s = 0.f;
#pragma unroll
        for (int w2 = 0; w2 < 16; w2++) s += ssum[w2];
        g_loss[fb] = logf(s) + bm - slog[0];
        __threadfence();
        int p = atomicAdd(&g_done, 1);
        s_last = (p == F * B - 1) ? 1 : 0;
    }
    __syncthreads();

    if (s_last) {
        __threadfence();                  // acquire: see all g_loss writes
        float v = (tid < F * B) ? g_loss[tid] : 0.f;
        v = warpsum(v);
        if (!l) ssum[w] = v;
        __syncthreads();
        if (tid == 0) {
            float tot = 0.f;
#pragma unroll
            for (int w2 = 0; w2 < 16; w2++) tot += ssum[w2];
            out[0] = tot * (1.0f / 128.0f);   // / (2 * BATCH_SIZE)
        }
    }
}

}  // namespace

extern "C" void kernel_launch(void* const* d_in, const int* in_sizes, int n_in,
                              void* d_out, int out_size) {
    const float* fi   = (const float*)d_in[0];
    const float* fj   = (const float*)d_in[1];
    const int*   ids  = (const int*)d_in[2];
    const int*   idxj = (const int*)d_in[3];
    const int*   idxk = (const int*)d_in[4];
    float* out = (float*)d_out;

    static bool attr_done = false;
    if (!attr_done) {
        cudaFuncSetAttribute(k_gram_mma, cudaFuncAttributeMaxDynamicSharedMemorySize,
                             GRAM_SMEM);
        attr_done = true;
    }

    k_prep<<<F * B, 256>>>(fi, fj);
    k_gram_mma<<<6 * 64, 256, GRAM_SMEM>>>();
    k_negls<<<F * B, 512>>>(ids, idxj, idxk, out);
}